// round 12
// baseline (speedup 1.0000x reference)
#include <cuda_runtime.h>
#include <math.h>
#include <float.h>

#define SB     1024
#define NB     32
#define NG     5
#define TK     5
#define EPSF   1e-7f
#define NLBLK  128
#define NTHR   256
#define NWARP  (NTHR / 32)
#define TOTB   (NB + NLBLK)
#define CAP    1024
#define NEGINF (-1e30f)
#define FULLM  0xffffffffu
#define IMAXU  0x7fffffffu
#define FIX    1099511627776.0f      /* 2^40 */
#define FIXINV (1.0f / 1099511627776.0f)
#define M56    ((1ULL << 56) - 1ULL)

__device__ unsigned long long g_pack = 0ULL;   // [63:56]=count, [55:0]=fixed-point sum

__device__ __forceinline__ float sigf(float x) {
    return __fdividef(1.0f, 1.0f + __expf(-x));
}

// strict total order: larger value first; ties -> smaller flat index first
__device__ __forceinline__ bool better(float s1, int i1, float s2, int i2) {
    return (s1 > s2) || (s1 == s2 && i1 < i2);
}

__device__ __forceinline__ void tryins(float* s5, int* i5, float v, int id) {
    if (v > s5[TK - 1] || (v == s5[TK - 1] && id < i5[TK - 1])) {
        float ts = v; int ti = id;
#pragma unroll
        for (int k = 0; k < TK; k++) {
            if (better(ts, ti, s5[k], i5[k])) {
                float a = s5[k]; int b = i5[k];
                s5[k] = ts; i5[k] = ti;
                ts = a; ti = b;
            }
        }
    }
}

__device__ __forceinline__ float wbce(float x, float tg) {
    float p = fminf(fmaxf(sigf(x), EPSF), 1.0f - EPSF);
    float b = -(tg * __logf(p) + (1.0f - tg) * __logf(1.0f - p));
    float d = fabsf(p - tg);
    return b * d * d;
}

__global__ void __launch_bounds__(NTHR)
crit_all(const float* __restrict__ fp, const float* __restrict__ sl,
         const float* __restrict__ ml, const float* __restrict__ el,
         const float* __restrict__ gt, const int* __restrict__ smsp,
         float* __restrict__ out) {
    __shared__ __align__(16) float ep[SB];
    __shared__ __align__(16) float cands[CAP];
    __shared__ int   candi[CAP];
    __shared__ __align__(8) float2 rpack[SB];   // {spi, bitcast(row)}
    __shared__ float warpM[NWARP];
    __shared__ float wtop[NWARP * TK];
    __shared__ float gtl[NG * 2];
    __shared__ int   smsl;
    __shared__ float fb_s[TK];
    __shared__ int   fb_i[TK];
    __shared__ int   cnt, rown;
    __shared__ float wsum[NWARP];

    const int t    = threadIdx.x;
    const int blk  = blockIdx.x;
    const int lane = t & 31;
    const int w    = t >> 5;

    float partial = 0.0f;   // thread 0's scaled, nonnegative block contribution

    if (blk < NB) {
        // ================= spans loss: one block per batch =================
        const int b = blk;
        if (t < NG * 2) gtl[t] = gt[b * NG * 2 + t];
        if (t == NG * 2) smsl = smsp[b];
        if (t == 0) { cnt = 0; rown = 0; }

        const float4* fp4 = ((const float4*)fp) + b * SB;
        float4 va = fp4[4 * t], vb = fp4[4 * t + 1], vc = fp4[4 * t + 2], vd = fp4[4 * t + 3];
        const float s0 = sigf(va.x), s1 = sigf(vb.x), s2 = sigf(vc.x), s3 = sigf(vd.x);
        const float e0 = sigf(va.z), e1 = sigf(vb.z), e2 = sigf(vc.z), e3 = sigf(vd.z);
        ep[4 * t] = e0; ep[4 * t + 1] = e1; ep[4 * t + 2] = e2; ep[4 * t + 3] = e3;

        // ---- suffix max of ep: warp inclusive-max scan + cross-warp tail ----
        float inc = fmaxf(fmaxf(e0, e1), fmaxf(e2, e3));
#pragma unroll
        for (int o = 1; o < 32; o <<= 1) {
            float v = __shfl_down_sync(FULLM, inc, o);
            if (lane + o < 32) inc = fmaxf(inc, v);
        }
        float excl = __shfl_down_sync(FULLM, inc, 1);
        if (lane == 31) excl = NEGINF;
        if (lane == 0) warpM[w] = inc;
        __syncthreads();                                    // (1)
        float suffW = NEGINF;
#pragma unroll
        for (int ww = 0; ww < NWARP; ww++)
            if (ww > w) suffW = fmaxf(suffW, warpM[ww]);
        const float tail = fmaxf(excl, suffW);
        const float sf3 = fmaxf(e3, tail);
        const float sf2 = fmaxf(e2, sf3);
        const float sf1 = fmaxf(e1, sf2);
        const float sf0 = fmaxf(e0, sf1);
        const float u0 = s0 * sf0, u1 = s1 * sf1, u2 = s2 * sf2, u3 = s3 * sf3;

        // ---- per-warp top-5 of u via redux (ballot-free over-pop) ----
        {
            float a0 = u0, a1 = u1, a2 = u2, a3 = u3;
            float wval = 0.0f;
#pragma unroll
            for (int r = 0; r < TK; r++) {
                float lm = fmaxf(fmaxf(a0, a1), fmaxf(a2, a3));
                unsigned m = __reduce_max_sync(FULLM, __float_as_uint(lm));
                if (__float_as_uint(lm) == m) {     // every holding lane pops one
                    if (__float_as_uint(a0) == m) a0 = 0.0f;
                    else if (__float_as_uint(a1) == m) a1 = 0.0f;
                    else if (__float_as_uint(a2) == m) a2 = 0.0f;
                    else a3 = 0.0f;
                }
                if (lane == r) wval = __uint_as_float(m);
            }
            if (lane < TK) wtop[w * TK + lane] = wval;
        }
        __syncthreads();                                    // (2)

        // ---- every warp merges the 40 warp-top values -> L (ballot-free) ----
        float L;
        {
            float a = wtop[lane < NWARP * TK ? lane : 0];
            if (lane >= NWARP * TK) a = 0.0f;
            float c = (32 + lane < NWARP * TK) ? wtop[32 + lane] : 0.0f;
            unsigned m = 0;
#pragma unroll
            for (int r = 0; r < TK; r++) {
                float lm = fmaxf(a, c);
                m = __reduce_max_sync(FULLM, __float_as_uint(lm));
                if (__float_as_uint(lm) == m) {
                    if (__float_as_uint(a) == m) a = 0.0f; else c = 0.0f;
                }
            }
            L = __uint_as_float(m);   // == exact global 5th on tie-free data
        }

        // ---- collect surviving rows (u_i >= L), packed {spi,row} ----
        {
            const float uu[4] = { u0, u1, u2, u3 };
            const float ss[4] = { s0, s1, s2, s3 };
#pragma unroll
            for (int k = 0; k < 4; k++) {
                if (uu[k] >= L) {
                    int p = atomicAdd(&rown, 1);
                    rpack[p] = make_float2(ss[k], __int_as_float(4 * t + k));
                }
            }
        }
        __syncthreads();                                    // (3)
        const int R = rown;

        // ---- scan with ep in REGISTERS: broadcast one packed row per iter ----
        {
            const int c0 = 4 * t, c1 = 4 * t + 1, c2 = 4 * t + 2, c3 = 4 * t + 3;
            float2 cur = (R > 0) ? rpack[0] : make_float2(0.0f, 0.0f);
            for (int r = 0; r < R; r++) {
                float2 nxt = (r + 1 < R) ? rpack[r + 1] : cur;   // prefetch
                const float spi = cur.x;
                const int   i   = __float_as_int(cur.y);
                const int base  = i << 10;
                float v0 = spi * e0, v1 = spi * e1, v2 = spi * e2, v3 = spi * e3;
                if (v0 >= L && c0 >= i) { int p = atomicAdd(&cnt, 1); if (p < CAP) { cands[p] = v0; candi[p] = base + c0; } }
                if (v1 >= L && c1 >= i) { int p = atomicAdd(&cnt, 1); if (p < CAP) { cands[p] = v1; candi[p] = base + c1; } }
                if (v2 >= L && c2 >= i) { int p = atomicAdd(&cnt, 1); if (p < CAP) { cands[p] = v2; candi[p] = base + c2; } }
                if (v3 >= L && c3 >= i) { int p = atomicAdd(&cnt, 1); if (p < CAP) { cands[p] = v3; candi[p] = base + c3; } }
                cur = nxt;
            }
        }
        __syncthreads();                                    // (4)
        const int C = cnt;

        if (C > CAP) {       // pathological fallback: exact serial scan (recompute sp)
            if (t == 0) {
                float s5[TK]; int i5[TK];
#pragma unroll
                for (int k = 0; k < TK; k++) { s5[k] = -1.0f; i5[k] = IMAXU; }
                for (int i = 0; i < SB; i++) {
                    float spi = sigf(fp4[i].x);
                    for (int j = i; j < SB; j++) tryins(s5, i5, spi * ep[j], (i << 10) + j);
                }
#pragma unroll
                for (int k = 0; k < TK; k++) { fb_s[k] = s5[k]; fb_i[k] = i5[k]; }
            }
            __syncthreads();
        }

        // ---- warp 0: final top-5 (exact redux-min tie-break) + GIoU ----
        if (t < 32) {
            float fs[TK]; int fi[TK];
            if (C <= CAP) {
                float s5[TK]; int i5[TK];
#pragma unroll
                for (int k = 0; k < TK; k++) { s5[k] = 0.0f; i5[k] = IMAXU; }
                for (int p = lane; p < C; p += 32) tryins(s5, i5, cands[p], candi[p]);
#pragma unroll
                for (int r = 0; r < TK; r++) {
                    unsigned vb_ = __float_as_uint(s5[0]);
                    unsigned m = __reduce_max_sync(FULLM, vb_);
                    unsigned idc = (vb_ == m) ? (unsigned)i5[0] : IMAXU;
                    unsigned widx = __reduce_min_sync(FULLM, idc);
                    if (vb_ == m && (unsigned)i5[0] == widx) {   // unique winner pops
#pragma unroll
                        for (int k = 0; k < TK - 1; k++) { s5[k] = s5[k + 1]; i5[k] = i5[k + 1]; }
                        s5[TK - 1] = 0.0f; i5[TK - 1] = IMAXU;
                    }
                    fs[r] = __uint_as_float(m); fi[r] = (int)widx;
                }
            } else {
#pragma unroll
                for (int k = 0; k < TK; k++) { fs[k] = fb_s[k]; fi[k] = fb_i[k]; }
            }

            float val = 0.0f;
            if (lane < TK) {
                float conf = fs[lane]; int fid = fi[lane];
                int i = fid >> 10, j = fid & (SB - 1);
                float smsf = (float)smsl;
                float pst = (float)i + smsf;
                float ped = (float)j + smsf;
                float best = -INFINITY;
#pragma unroll
                for (int g = 0; g < NG; g++) {
                    float gst = gtl[2 * g + 0];
                    float ged = gtl[2 * g + 1];
                    float inter = fmaxf(fminf(ped, ged) - fmaxf(pst, gst), 0.0f);
                    float uni   = (ped - pst) + (ged - gst) - inter;
                    float iou   = __fdividef(inter, fmaxf(uni, EPSF));
                    float enc   = fmaxf(fmaxf(ped, ged) - fminf(pst, gst), 0.0f);
                    float gi    = iou - __fdividef(enc - uni, fmaxf(enc, EPSF));
                    best = fmaxf(best, gi);
                }
                float d = conf - best;
                val = d * d;
            }
            val += __shfl_down_sync(FULLM, val, 4);
            val += __shfl_down_sync(FULLM, val, 2);
            val += __shfl_down_sync(FULLM, val, 1);
            if (lane == 0) partial = val * (1.0f / 160.0f);
        }
    } else {
        // ================= label loss: one element per thread =================
        const int lb = blk - NB;
        const int gid = lb * NTHR + t;
        float4 v = ((const float4*)fp)[gid];
        float acc = wbce(v.x, sl[gid]) + wbce(v.y, ml[gid]) + wbce(v.z, el[gid]);
#pragma unroll
        for (int off = 16; off; off >>= 1)
            acc += __shfl_down_sync(FULLM, acc, off);
        if (lane == 0) wsum[w] = acc;
        __syncthreads();
        if (t == 0) {
            float s = 0.0f;
#pragma unroll
            for (int ww = 0; ww < NWARP; ww++) s += wsum[ww];
            partial = s * (1.0f / 32768.0f);
        }
    }

    // ===== tail: ONE packed 64-bit atomic; last adder emits from return value =====
    if (t == 0) {
        unsigned long long ticket =
            (1ULL << 56) + (unsigned long long)(partial * FIX);   // partial >= 0
        unsigned long long old = atomicAdd(&g_pack, ticket);
        if ((old >> 56) == (unsigned long long)(TOTB - 1)) {
            unsigned long long total = (old + ticket) & M56;
            out[0] = (float)total * FIXINV;
            g_pack = 0ULL;     // reset for next graph replay
        }
    }
}

extern "C" void kernel_launch(void* const* d_in, const int* in_sizes, int n_in,
                              void* d_out, int out_size) {
    const float* fp  = (const float*)d_in[0];
    const float* sl  = (const float*)d_in[1];
    const float* ml  = (const float*)d_in[2];
    const float* el  = (const float*)d_in[3];
    const float* gt  = (const float*)d_in[4];
    const int*   sms = (const int*)d_in[5];

    crit_all<<<TOTB, NTHR>>>(fp, sl, ml, el, gt, sms, (float*)d_out);
}

// round 13
// speedup vs baseline: 1.0637x; 1.0637x over previous
#include <cuda_runtime.h>
#include <math.h>
#include <float.h>

#define SB     1024
#define NB     32
#define NG     5
#define TK     5
#define EPSF   1e-7f
#define NLBLK  64                    // 64*256*2 = 32768 -> 2 elems/thread, ONE wave total
#define NTHR   256
#define NWARP  (NTHR / 32)
#define TOTB   (NB + NLBLK)          // 96 blocks < 148 SMs
#define CAP    1024
#define NEGINF (-1e30f)
#define FULLM  0xffffffffu
#define IMAXU  0x7fffffffu
#define FIX    1099511627776.0f      /* 2^40 */
#define FIXINV (1.0f / 1099511627776.0f)
#define M56    ((1ULL << 56) - 1ULL)

__device__ unsigned long long g_pack = 0ULL;   // [63:56]=count, [55:0]=fixed-point sum

__device__ __forceinline__ float sigf(float x) {
    return __fdividef(1.0f, 1.0f + __expf(-x));
}

// strict total order: larger value first; ties -> smaller flat index first
__device__ __forceinline__ bool better(float s1, int i1, float s2, int i2) {
    return (s1 > s2) || (s1 == s2 && i1 < i2);
}

__device__ __forceinline__ void tryins(float* s5, int* i5, float v, int id) {
    if (v > s5[TK - 1] || (v == s5[TK - 1] && id < i5[TK - 1])) {
        float ts = v; int ti = id;
#pragma unroll
        for (int k = 0; k < TK; k++) {
            if (better(ts, ti, s5[k], i5[k])) {
                float a = s5[k]; int b = i5[k];
                s5[k] = ts; i5[k] = ti;
                ts = a; ti = b;
            }
        }
    }
}

__device__ __forceinline__ float wbce(float x, float tg) {
    float p = fminf(fmaxf(sigf(x), EPSF), 1.0f - EPSF);
    float b = -(tg * __logf(p) + (1.0f - tg) * __logf(1.0f - p));
    float d = fabsf(p - tg);
    return b * d * d;
}

__global__ void __launch_bounds__(NTHR)
crit_all(const float* __restrict__ fp, const float* __restrict__ sl,
         const float* __restrict__ ml, const float* __restrict__ el,
         const float* __restrict__ gt, const int* __restrict__ smsp,
         float* __restrict__ out) {
    __shared__ __align__(16) float ep[SB];
    __shared__ __align__(16) float cands[CAP];
    __shared__ int   candi[CAP];
    __shared__ __align__(8) float2 rpack[SB];   // {spi, bitcast(row)}
    __shared__ float warpM[NWARP];
    __shared__ float wtop[NWARP * TK];
    __shared__ float gtl[NG * 2];
    __shared__ int   smsl;
    __shared__ float fb_s[TK];
    __shared__ int   fb_i[TK];
    __shared__ int   cnt, rown;
    __shared__ float wsum[NWARP];

    const int t    = threadIdx.x;
    const int blk  = blockIdx.x;
    const int lane = t & 31;
    const int w    = t >> 5;

    float partial = 0.0f;   // thread 0's scaled, nonnegative block contribution

    if (blk < NB) {
        // ================= spans loss: one block per batch =================
        const int b = blk;
        if (t < NG * 2) gtl[t] = gt[b * NG * 2 + t];
        if (t == NG * 2) smsl = smsp[b];
        if (t == 0) { cnt = 0; rown = 0; }

        const float4* fp4 = ((const float4*)fp) + b * SB;
        float4 va = fp4[4 * t], vb = fp4[4 * t + 1], vc = fp4[4 * t + 2], vd = fp4[4 * t + 3];
        const float s0 = sigf(va.x), s1 = sigf(vb.x), s2 = sigf(vc.x), s3 = sigf(vd.x);
        const float e0 = sigf(va.z), e1 = sigf(vb.z), e2 = sigf(vc.z), e3 = sigf(vd.z);
        ep[4 * t] = e0; ep[4 * t + 1] = e1; ep[4 * t + 2] = e2; ep[4 * t + 3] = e3;

        // ---- suffix max of ep: warp inclusive-max scan + cross-warp tail ----
        float inc = fmaxf(fmaxf(e0, e1), fmaxf(e2, e3));
#pragma unroll
        for (int o = 1; o < 32; o <<= 1) {
            float v = __shfl_down_sync(FULLM, inc, o);
            if (lane + o < 32) inc = fmaxf(inc, v);
        }
        float excl = __shfl_down_sync(FULLM, inc, 1);
        if (lane == 31) excl = NEGINF;
        if (lane == 0) warpM[w] = inc;
        __syncthreads();                                    // (1)
        float suffW = NEGINF;
#pragma unroll
        for (int ww = 0; ww < NWARP; ww++)
            if (ww > w) suffW = fmaxf(suffW, warpM[ww]);
        const float tail = fmaxf(excl, suffW);
        const float sf3 = fmaxf(e3, tail);
        const float sf2 = fmaxf(e2, sf3);
        const float sf1 = fmaxf(e1, sf2);
        const float sf0 = fmaxf(e0, sf1);
        const float u0 = s0 * sf0, u1 = s1 * sf1, u2 = s2 * sf2, u3 = s3 * sf3;

        // ---- per-warp top-5 of u via redux (ballot-free over-pop) ----
        {
            float a0 = u0, a1 = u1, a2 = u2, a3 = u3;
            float wval = 0.0f;
#pragma unroll
            for (int r = 0; r < TK; r++) {
                float lm = fmaxf(fmaxf(a0, a1), fmaxf(a2, a3));
                unsigned m = __reduce_max_sync(FULLM, __float_as_uint(lm));
                if (__float_as_uint(lm) == m) {     // every holding lane pops one
                    if (__float_as_uint(a0) == m) a0 = 0.0f;
                    else if (__float_as_uint(a1) == m) a1 = 0.0f;
                    else if (__float_as_uint(a2) == m) a2 = 0.0f;
                    else a3 = 0.0f;
                }
                if (lane == r) wval = __uint_as_float(m);
            }
            if (lane < TK) wtop[w * TK + lane] = wval;
        }
        __syncthreads();                                    // (2)

        // ---- every warp merges the 40 warp-top values -> L (ballot-free) ----
        float L;
        {
            float a = wtop[lane < NWARP * TK ? lane : 0];
            if (lane >= NWARP * TK) a = 0.0f;
            float c = (32 + lane < NWARP * TK) ? wtop[32 + lane] : 0.0f;
            unsigned m = 0;
#pragma unroll
            for (int r = 0; r < TK; r++) {
                float lm = fmaxf(a, c);
                m = __reduce_max_sync(FULLM, __float_as_uint(lm));
                if (__float_as_uint(lm) == m) {
                    if (__float_as_uint(a) == m) a = 0.0f; else c = 0.0f;
                }
            }
            L = __uint_as_float(m);   // == exact global 5th on tie-free data
        }

        // ---- collect surviving rows (u_i >= L), packed {spi,row} ----
        {
            const float uu[4] = { u0, u1, u2, u3 };
            const float ss[4] = { s0, s1, s2, s3 };
#pragma unroll
            for (int k = 0; k < 4; k++) {
                if (uu[k] >= L) {
                    int p = atomicAdd(&rown, 1);
                    rpack[p] = make_float2(ss[k], __int_as_float(4 * t + k));
                }
            }
        }
        __syncthreads();                                    // (3)
        const int R = rown;

        // ---- scan with ep in REGISTERS: broadcast one packed row per iter ----
        {
            const int c0 = 4 * t, c1 = 4 * t + 1, c2 = 4 * t + 2, c3 = 4 * t + 3;
            float2 cur = (R > 0) ? rpack[0] : make_float2(0.0f, 0.0f);
            for (int r = 0; r < R; r++) {
                float2 nxt = (r + 1 < R) ? rpack[r + 1] : cur;   // prefetch
                const float spi = cur.x;
                const int   i   = __float_as_int(cur.y);
                const int base  = i << 10;
                float v0 = spi * e0, v1 = spi * e1, v2 = spi * e2, v3 = spi * e3;
                if (v0 >= L && c0 >= i) { int p = atomicAdd(&cnt, 1); if (p < CAP) { cands[p] = v0; candi[p] = base + c0; } }
                if (v1 >= L && c1 >= i) { int p = atomicAdd(&cnt, 1); if (p < CAP) { cands[p] = v1; candi[p] = base + c1; } }
                if (v2 >= L && c2 >= i) { int p = atomicAdd(&cnt, 1); if (p < CAP) { cands[p] = v2; candi[p] = base + c2; } }
                if (v3 >= L && c3 >= i) { int p = atomicAdd(&cnt, 1); if (p < CAP) { cands[p] = v3; candi[p] = base + c3; } }
                cur = nxt;
            }
        }
        __syncthreads();                                    // (4)
        const int C = cnt;

        if (C > CAP) {       // pathological fallback: exact serial scan (recompute sp)
            if (t == 0) {
                float s5[TK]; int i5[TK];
#pragma unroll
                for (int k = 0; k < TK; k++) { s5[k] = -1.0f; i5[k] = IMAXU; }
                for (int i = 0; i < SB; i++) {
                    float spi = sigf(fp4[i].x);
                    for (int j = i; j < SB; j++) tryins(s5, i5, spi * ep[j], (i << 10) + j);
                }
#pragma unroll
                for (int k = 0; k < TK; k++) { fb_s[k] = s5[k]; fb_i[k] = i5[k]; }
            }
            __syncthreads();
        }

        // ---- warp 0: final top-5 (exact redux-min tie-break) + GIoU ----
        if (t < 32) {
            float fs[TK]; int fi[TK];
            if (C <= CAP) {
                float s5[TK]; int i5[TK];
#pragma unroll
                for (int k = 0; k < TK; k++) { s5[k] = 0.0f; i5[k] = IMAXU; }
                for (int p = lane; p < C; p += 32) tryins(s5, i5, cands[p], candi[p]);
#pragma unroll
                for (int r = 0; r < TK; r++) {
                    unsigned vb_ = __float_as_uint(s5[0]);
                    unsigned m = __reduce_max_sync(FULLM, vb_);
                    unsigned idc = (vb_ == m) ? (unsigned)i5[0] : IMAXU;
                    unsigned widx = __reduce_min_sync(FULLM, idc);
                    if (vb_ == m && (unsigned)i5[0] == widx) {   // unique winner pops
#pragma unroll
                        for (int k = 0; k < TK - 1; k++) { s5[k] = s5[k + 1]; i5[k] = i5[k + 1]; }
                        s5[TK - 1] = 0.0f; i5[TK - 1] = IMAXU;
                    }
                    fs[r] = __uint_as_float(m); fi[r] = (int)widx;
                }
            } else {
#pragma unroll
                for (int k = 0; k < TK; k++) { fs[k] = fb_s[k]; fi[k] = fb_i[k]; }
            }

            float val = 0.0f;
            if (lane < TK) {
                float conf = fs[lane]; int fid = fi[lane];
                int i = fid >> 10, j = fid & (SB - 1);
                float smsf = (float)smsl;
                float pst = (float)i + smsf;
                float ped = (float)j + smsf;
                float best = -INFINITY;
#pragma unroll
                for (int g = 0; g < NG; g++) {
                    float gst = gtl[2 * g + 0];
                    float ged = gtl[2 * g + 1];
                    float inter = fmaxf(fminf(ped, ged) - fmaxf(pst, gst), 0.0f);
                    float uni   = (ped - pst) + (ged - gst) - inter;
                    float iou   = __fdividef(inter, fmaxf(uni, EPSF));
                    float enc   = fmaxf(fmaxf(ped, ged) - fminf(pst, gst), 0.0f);
                    float gi    = iou - __fdividef(enc - uni, fmaxf(enc, EPSF));
                    best = fmaxf(best, gi);
                }
                float d = conf - best;
                val = d * d;
            }
            val += __shfl_down_sync(FULLM, val, 4);
            val += __shfl_down_sync(FULLM, val, 2);
            val += __shfl_down_sync(FULLM, val, 1);
            if (lane == 0) partial = val * (1.0f / 160.0f);
        }
    } else {
        // ====== label loss: exactly two elements per thread, single wave ======
        const int lb = blk - NB;
        const int gidA = lb * NTHR + t;            // < 16384
        const int gidB = gidA + NLBLK * NTHR;      // < 32768
        // issue all 8 loads before any compute (independent -> overlapped latency)
        float4 vA = ((const float4*)fp)[gidA];
        float4 vB = ((const float4*)fp)[gidB];
        float slA = sl[gidA], mlA = ml[gidA], elA = el[gidA];
        float slB = sl[gidB], mlB = ml[gidB], elB = el[gidB];
        float acc = wbce(vA.x, slA) + wbce(vA.y, mlA) + wbce(vA.z, elA)
                  + wbce(vB.x, slB) + wbce(vB.y, mlB) + wbce(vB.z, elB);
#pragma unroll
        for (int off = 16; off; off >>= 1)
            acc += __shfl_down_sync(FULLM, acc, off);
        if (lane == 0) wsum[w] = acc;
        __syncthreads();
        if (t == 0) {
            float s = 0.0f;
#pragma unroll
            for (int ww = 0; ww < NWARP; ww++) s += wsum[ww];
            partial = s * (1.0f / 32768.0f);
        }
    }

    // ===== tail: ONE packed 64-bit atomic; last adder emits from return value =====
    if (t == 0) {
        unsigned long long ticket =
            (1ULL << 56) + (unsigned long long)(partial * FIX);   // partial >= 0
        unsigned long long old = atomicAdd(&g_pack, ticket);
        if ((old >> 56) == (unsigned long long)(TOTB - 1)) {
            unsigned long long total = (old + ticket) & M56;
            out[0] = (float)total * FIXINV;
            g_pack = 0ULL;     // reset for next graph replay
        }
    }
}

extern "C" void kernel_launch(void* const* d_in, const int* in_sizes, int n_in,
                              void* d_out, int out_size) {
    const float* fp  = (const float*)d_in[0];
    const float* sl  = (const float*)d_in[1];
    const float* ml  = (const float*)d_in[2];
    const float* el  = (const float*)d_in[3];
    const float* gt  = (const float*)d_in[4];
    const int*   sms = (const int*)d_in[5];

    crit_all<<<TOTB, NTHR>>>(fp, sl, ml, el, gt, sms, (float*)d_out);
}